// round 1
// baseline (speedup 1.0000x reference)
#include <cuda_runtime.h>
#include <cuda_bf16.h>

// Problem shapes (fixed for this problem instance)
#define Bb    8
#define Ssz   2048
#define Hd    512      // hidden
#define Gg    2        // groups
#define Vv    320      // vars per group
#define Dd    256      // codevector dim
#define Nrows (Bb*Ssz)     // 16384
#define GVc   (Gg*Vv)      // 640

typedef unsigned long long ull;

// Scratch (allocation-free rule: __device__ globals)
__device__ float g_logits[(size_t)Nrows * GVc];   // ~41.9 MB
__device__ float g_acc[GVc];                      // masked softmax marginals (unnormalized)

// ---------------------------------------------------------------------------
// packed fp32x2 helpers (sm_100+)
// ---------------------------------------------------------------------------
__device__ __forceinline__ void fma2(ull &d, ull a, ull b) {
    asm("fma.rn.f32x2 %0, %1, %2, %0;" : "+l"(d) : "l"(a), "l"(b));
}
__device__ __forceinline__ ull pack2(float x, float y) {
    ull r; asm("mov.b64 %0, {%1, %2};" : "=l"(r) : "f"(x), "f"(y)); return r;
}
__device__ __forceinline__ float2 unpack2(ull v) {
    float2 r; asm("mov.b64 {%0, %1}, %2;" : "=f"(r.x), "=f"(r.y) : "l"(v)); return r;
}

// ---------------------------------------------------------------------------
// Kernel 0: zero the marginal accumulator (graph-replayed every launch)
// ---------------------------------------------------------------------------
__global__ void zero_acc_kernel() {
    if (threadIdx.x < GVc) g_acc[threadIdx.x] = 0.0f;
}

// ---------------------------------------------------------------------------
// Kernel 1: fp32 GEMM  logits[16384,640] = hs[16384,512] @ W[512,640] + b
// 128x128 block tile, BK=16, 256 threads, 8x8 per-thread microtile,
// inner product via packed fma.rn.f32x2 (2 FMA / FMA-pipe slot).
// ---------------------------------------------------------------------------
#define BM 128
#define BN 128
#define BK 16
#define TM 8
#define TN 8

__global__ __launch_bounds__(256) void gemm_kernel(
    const float* __restrict__ A,      // [Nrows, Hd]
    const float* __restrict__ W,      // [Hd, GVc]
    const float* __restrict__ bias)   // [GVc]
{
    __shared__ __align__(16) float As[BK][BM + 8];  // +8 pad: keeps float4 rows 16B-aligned
    __shared__ __align__(16) float Bs[BK][BN];

    const int tid = threadIdx.x;
    const int rowBase = blockIdx.y * BM;
    const int colBase = blockIdx.x * BN;
    const int tr = tid >> 4;   // 0..15
    const int tc = tid & 15;   // 0..15

    ull acc[TM][TN/2];
    #pragma unroll
    for (int i = 0; i < TM; i++)
        #pragma unroll
        for (int j = 0; j < TN/2; j++) acc[i][j] = 0ULL;

    for (int kt = 0; kt < Hd; kt += BK) {
        // load A tile 128x16 (512 float4), store k-major into As
        #pragma unroll
        for (int l = 0; l < 2; l++) {
            int f  = tid + l * 256;
            int ar = f >> 2;
            int ac = (f & 3) * 4;
            float4 v = *reinterpret_cast<const float4*>(
                &A[(size_t)(rowBase + ar) * Hd + kt + ac]);
            As[ac + 0][ar] = v.x; As[ac + 1][ar] = v.y;
            As[ac + 2][ar] = v.z; As[ac + 3][ar] = v.w;
        }
        // load B tile 16x128 (512 float4), natural layout
        #pragma unroll
        for (int l = 0; l < 2; l++) {
            int f  = tid + l * 256;
            int br = f >> 5;
            int bc = (f & 31) * 4;
            *reinterpret_cast<float4*>(&Bs[br][bc]) =
                *reinterpret_cast<const float4*>(
                    &W[(size_t)(kt + br) * GVc + colBase + bc]);
        }
        __syncthreads();

        #pragma unroll
        for (int kk = 0; kk < BK; kk++) {
            // A fragment: 8 contiguous floats -> 2 float4 loads, then pack (a,a)
            float4 a0 = *reinterpret_cast<const float4*>(&As[kk][tr * TM]);
            float4 a1 = *reinterpret_cast<const float4*>(&As[kk][tr * TM + 4]);
            ull ap[TM];
            ap[0] = pack2(a0.x, a0.x); ap[1] = pack2(a0.y, a0.y);
            ap[2] = pack2(a0.z, a0.z); ap[3] = pack2(a0.w, a0.w);
            ap[4] = pack2(a1.x, a1.x); ap[5] = pack2(a1.y, a1.y);
            ap[6] = pack2(a1.z, a1.z); ap[7] = pack2(a1.w, a1.w);
            // B fragment: 8 contiguous floats as 4x 64-bit
            const ull* bptr = reinterpret_cast<const ull*>(&Bs[kk][tc * TN]);
            ull bp[TN/2];
            #pragma unroll
            for (int j = 0; j < TN/2; j++) bp[j] = bptr[j];
            #pragma unroll
            for (int i = 0; i < TM; i++)
                #pragma unroll
                for (int j = 0; j < TN/2; j++)
                    fma2(acc[i][j], ap[i], bp[j]);
        }
        __syncthreads();
    }

    // epilogue: add bias, write logits
    float bvals[TN];
    #pragma unroll
    for (int j = 0; j < TN; j++) bvals[j] = bias[colBase + tc * TN + j];
    #pragma unroll
    for (int i = 0; i < TM; i++) {
        int r = rowBase + tr * TM + i;
        float o[TN];
        #pragma unroll
        for (int j = 0; j < TN/2; j++) {
            float2 v = unpack2(acc[i][j]);
            o[2*j]   = v.x + bvals[2*j];
            o[2*j+1] = v.y + bvals[2*j+1];
        }
        float4* dst = reinterpret_cast<float4*>(
            &g_logits[(size_t)r * GVc + colBase + tc * TN]);
        dst[0] = make_float4(o[0], o[1], o[2], o[3]);
        dst[1] = make_float4(o[4], o[5], o[6], o[7]);
    }
}

// ---------------------------------------------------------------------------
// Kernel 2: per-(n,g) row processing. One warp per row:
//  - argmax(logit + gumbel) -> one-hot codevector gather (float4)
//  - masked softmax(logit) accumulated into shared [640], then global atomics
// ---------------------------------------------------------------------------
#define RPB 64   // (n,g) rows per block: 8 warps x 8 rows

__global__ __launch_bounds__(256) void rows_kernel(
    const float* __restrict__ gumbels,      // [Nrows*Gg, Vv]
    const int*   __restrict__ mask,         // [Nrows]
    const float* __restrict__ codevectors,  // [Gg*Vv, Dd/Gg]
    float*       __restrict__ out)          // [Nrows, Dd] (+ perplexity at end)
{
    __shared__ float sAcc[GVc];
    const int tid  = threadIdx.x;
    const int lane = tid & 31;
    const int warp = tid >> 5;

    for (int i = tid; i < GVc; i += 256) sAcc[i] = 0.0f;
    __syncthreads();

    const int base = blockIdx.x * RPB;
    for (int rr = warp; rr < RPB; rr += 8) {
        const int row = base + rr;       // row = n*Gg + g
        const int n = row >> 1;
        const int g = row & 1;
        const float* lrow = &g_logits[(size_t)n * GVc + g * Vv];
        const float* grow = &gumbels[(size_t)row * Vv];

        float lv[10], ev[10];
        float bestv = -1e30f; int besti = 0;
        float mx = -1e30f;
        #pragma unroll
        for (int t = 0; t < 10; t++) {
            int v = lane + 32 * t;
            float x = lrow[v];
            lv[t] = x;
            float s = x + grow[v];
            if (s > bestv) { bestv = s; besti = v; }
            mx = fmaxf(mx, x);
        }
        // warp reductions: argmax of (l+g), max of l
        #pragma unroll
        for (int off = 16; off; off >>= 1) {
            float ov = __shfl_xor_sync(0xffffffffu, bestv, off);
            int   oi = __shfl_xor_sync(0xffffffffu, besti, off);
            if (ov > bestv || (ov == bestv && oi < besti)) { bestv = ov; besti = oi; }
            mx = fmaxf(mx, __shfl_xor_sync(0xffffffffu, mx, off));
        }
        // softmax(l) for perplexity marginals
        float sum = 0.0f;
        #pragma unroll
        for (int t = 0; t < 10; t++) { ev[t] = __expf(lv[t] - mx); sum += ev[t]; }
        #pragma unroll
        for (int off = 16; off; off >>= 1) sum += __shfl_xor_sync(0xffffffffu, sum, off);
        const float inv = 1.0f / sum;

        if (mask[n] != 0) {
            #pragma unroll
            for (int t = 0; t < 10; t++)
                atomicAdd(&sAcc[g * Vv + lane + 32 * t], ev[t] * inv);
        }

        // one-hot codevector gather: 128 floats = 32 float4, one per lane
        const float4* src = reinterpret_cast<const float4*>(
            &codevectors[((size_t)g * Vv + besti) * (Dd / Gg)]);
        float4* dst = reinterpret_cast<float4*>(
            &out[(size_t)n * Dd + g * (Dd / Gg)]);
        dst[lane] = src[lane];
    }

    __syncthreads();
    for (int i = tid; i < GVc; i += 256) atomicAdd(&g_acc[i], sAcc[i]);
}

// ---------------------------------------------------------------------------
// Kernel 3: finalize perplexity
// ---------------------------------------------------------------------------
__global__ __launch_bounds__(256) void finalize_kernel(
    const int* __restrict__ mask, float* __restrict__ out, int out_size)
{
    __shared__ float  red[256];
    __shared__ double er0[256];
    __shared__ double er1[256];
    const int tid = threadIdx.x;

    float cnt = 0.0f;
    for (int i = tid; i < Nrows; i += 256) cnt += (mask[i] != 0) ? 1.0f : 0.0f;
    red[tid] = cnt; __syncthreads();
    for (int s = 128; s > 0; s >>= 1) {
        if (tid < s) red[tid] += red[tid + s];
        __syncthreads();
    }
    const double msum = (double)red[0];

    double e0 = 0.0, e1 = 0.0;
    for (int i = tid; i < GVc; i += 256) {
        double marg = (double)g_acc[i] / msum;
        double t = marg * log(marg + 1e-7);
        if (i < Vv) e0 += t; else e1 += t;
    }
    er0[tid] = e0; er1[tid] = e1; __syncthreads();
    for (int s = 128; s > 0; s >>= 1) {
        if (tid < s) { er0[tid] += er0[tid + s]; er1[tid] += er1[tid + s]; }
        __syncthreads();
    }
    if (tid == 0) {
        double p = exp(-er0[0]) + exp(-er1[0]);
        out[out_size - 1] = (float)p;
    }
}

// ---------------------------------------------------------------------------
extern "C" void kernel_launch(void* const* d_in, const int* in_sizes, int n_in,
                              void* d_out, int out_size)
{
    (void)in_sizes; (void)n_in;
    const float* hs   = (const float*)d_in[0];   // [8,2048,512] f32
    const int*   mask = (const int*)  d_in[1];   // [8,2048] (bool -> int32 assumed)
    const float* W    = (const float*)d_in[2];   // [512, 640]
    const float* bias = (const float*)d_in[3];   // [640]
    const float* cb   = (const float*)d_in[4];   // [1, 640, 128]
    const float* gmb  = (const float*)d_in[5];   // [32768, 320]
    float* out = (float*)d_out;

    zero_acc_kernel<<<1, GVc>>>();

    dim3 ggrid(GVc / BN, Nrows / BM);  // (5, 128)
    gemm_kernel<<<ggrid, 256>>>(hs, W, bias);

    rows_kernel<<<(Nrows * Gg) / RPB, 256>>>(gmb, mask, cb, out);

    finalize_kernel<<<1, 256>>>(mask, out, out_size);
}

// round 3
// speedup vs baseline: 2.0435x; 2.0435x over previous
#include <cuda_runtime.h>
#include <cuda_bf16.h>
#include <cstdint>

// Problem shapes
#define Nrows 16384
#define Hd    512
#define Gg    2
#define Vv    320
#define Dd    256
#define GVc   640

// ---------------------------------------------------------------------------
// Device scratch
// ---------------------------------------------------------------------------
__device__ float g_logits[(size_t)Nrows * GVc];                 // 41.9 MB
__device__ __nv_bfloat16 g_A_hi[(size_t)Nrows * Hd];            // 16 MB
__device__ __nv_bfloat16 g_A_lo[(size_t)Nrows * Hd];            // 16 MB
__device__ __nv_bfloat16 g_Wt_hi[(size_t)GVc * Hd];             // 0.65 MB
__device__ __nv_bfloat16 g_Wt_lo[(size_t)GVc * Hd];
__device__ float g_acc[GVc];
__device__ float g_maskcnt;

// ---------------------------------------------------------------------------
// Helpers (baseline ISA only: sm_80-class PTX)
// ---------------------------------------------------------------------------
__device__ __forceinline__ uint32_t smem_u32(const void* p) {
    uint32_t a;
    asm("{ .reg .u64 t; cvta.to.shared.u64 t, %1; cvt.u32.u64 %0, t; }" : "=r"(a) : "l"(p));
    return a;
}
#define CP_ASYNC16(dst, src) \
    asm volatile("cp.async.cg.shared.global [%0], [%1], 16;" :: "r"(dst), "l"(src) : "memory")
#define CP_COMMIT() asm volatile("cp.async.commit_group;" ::: "memory")
#define CP_WAIT2()  asm volatile("cp.async.wait_group 2;" ::: "memory")
#define CP_WAIT0()  asm volatile("cp.async.wait_group 0;" ::: "memory")

#define LDSM_X4(r0, r1, r2, r3, a) \
    asm volatile("ldmatrix.sync.aligned.m8n8.x4.shared.b16 {%0,%1,%2,%3}, [%4];" \
        : "=r"(r0), "=r"(r1), "=r"(r2), "=r"(r3) : "r"(a))

#define MMA_BF16(c, a, b) \
    asm volatile("mma.sync.aligned.m16n8k16.row.col.f32.bf16.bf16.f32 " \
        "{%0,%1,%2,%3}, {%4,%5,%6,%7}, {%8,%9}, {%0,%1,%2,%3};" \
        : "+f"((c)[0]), "+f"((c)[1]), "+f"((c)[2]), "+f"((c)[3]) \
        : "r"((a)[0]), "r"((a)[1]), "r"((a)[2]), "r"((a)[3]), "r"((b)[0]), "r"((b)[1]))

#define SW64(o) ((o) ^ (((o) >> 3) & 0x30))

// ---------------------------------------------------------------------------
// Prep kernels
// ---------------------------------------------------------------------------
__global__ __launch_bounds__(256) void prep_W(const float* __restrict__ W) {
    int idx = blockIdx.x * 256 + threadIdx.x;        // 0..327679
    if (idx < GVc) g_acc[idx] = 0.0f;
    if (idx == 0) g_maskcnt = 0.0f;
    float x = W[idx];
    int k = idx / GVc, n = idx % GVc;
    __nv_bfloat16 h = __float2bfloat16_rn(x);
    float r = x - __bfloat162float(h);
    g_Wt_hi[(size_t)n * Hd + k] = h;
    g_Wt_lo[(size_t)n * Hd + k] = __float2bfloat16_rn(r);
}

__global__ __launch_bounds__(256) void prep_A(const float* __restrict__ A) {
    size_t idx = (size_t)blockIdx.x * 256 + threadIdx.x;   // over float4's: 2,097,152
    float4 v = reinterpret_cast<const float4*>(A)[idx];
    __nv_bfloat16 h0 = __float2bfloat16_rn(v.x), h1 = __float2bfloat16_rn(v.y);
    __nv_bfloat16 h2 = __float2bfloat16_rn(v.z), h3 = __float2bfloat16_rn(v.w);
    __nv_bfloat162 hi01; hi01.x = h0; hi01.y = h1;
    __nv_bfloat162 hi23; hi23.x = h2; hi23.y = h3;
    __nv_bfloat162 lo01, lo23;
    lo01.x = __float2bfloat16_rn(v.x - __bfloat162float(h0));
    lo01.y = __float2bfloat16_rn(v.y - __bfloat162float(h1));
    lo23.x = __float2bfloat16_rn(v.z - __bfloat162float(h2));
    lo23.y = __float2bfloat16_rn(v.w - __bfloat162float(h3));
    reinterpret_cast<__nv_bfloat162*>(g_A_hi)[idx * 2 + 0] = hi01;
    reinterpret_cast<__nv_bfloat162*>(g_A_hi)[idx * 2 + 1] = hi23;
    reinterpret_cast<__nv_bfloat162*>(g_A_lo)[idx * 2 + 0] = lo01;
    reinterpret_cast<__nv_bfloat162*>(g_A_lo)[idx * 2 + 1] = lo23;
}

__global__ __launch_bounds__(256) void mask_kernel(const int* __restrict__ mask) {
    __shared__ float red[256];
    int tid = threadIdx.x;
    int4 m = reinterpret_cast<const int4*>(mask)[blockIdx.x * 256 + tid];
    float c = (m.x != 0) + (m.y != 0) + (m.z != 0) + (m.w != 0);
    red[tid] = c; __syncthreads();
    for (int s = 128; s > 0; s >>= 1) { if (tid < s) red[tid] += red[tid + s]; __syncthreads(); }
    if (tid == 0) atomicAdd(&g_maskcnt, red[0]);  // integer-valued floats: order-exact
}

// ---------------------------------------------------------------------------
// bf16x3 GEMM via mma.sync: logits[16384,640] = A @ W + bias
// 128x128 CTA tile, BK=32, 4-stage cp.async pipeline, SW64 smem swizzle.
// ---------------------------------------------------------------------------
#define NSTAGE 4
#define NCHUNK 16
#define STAGE_BYTES 32768
#define AHI_OFF 0
#define ALO_OFF 8192
#define BHI_OFF 16384
#define BLO_OFF 24576
#define GEMM_SMEM (NSTAGE * STAGE_BYTES + 1024)

__global__ __launch_bounds__(256, 1) void gemm_bf16x3(const float* __restrict__ bias) {
    extern __shared__ char dsm[];
    const uint32_t raw = smem_u32(dsm);
    const uint32_t sb = (raw + 1023u) & ~1023u;

    const int tid = threadIdx.x;
    const int wid = tid >> 5, lane = tid & 31;
    const int rowBase = blockIdx.y * 128;
    const int colBase = blockIdx.x * 128;
    const int warpM = (wid & 1) * 64;
    const int warpN = (wid >> 1) * 32;

    const __nv_bfloat16* __restrict__ Ah = g_A_hi;
    const __nv_bfloat16* __restrict__ Al = g_A_lo;
    const __nv_bfloat16* __restrict__ Bh = g_Wt_hi;
    const __nv_bfloat16* __restrict__ Bl = g_Wt_lo;

    // per-thread load coords (two 16B chunks per matrix per stage)
    const int r0 = tid >> 2,          c0 = tid & 3;          // chunk 0: rows 0..63
    const int r1 = (tid + 256) >> 2,  c1 = tid & 3;          // chunk 1: rows 64..127

    auto load_stage = [&](int ck) {
        const int st = ck & 3;
        const uint32_t so = sb + st * STAGE_BYTES;
        const int kt = ck * 32;
        // A hi/lo
        {
            const __nv_bfloat16* s0 = &Ah[(size_t)(rowBase + r0) * Hd + kt + c0 * 8];
            const __nv_bfloat16* s1 = &Ah[(size_t)(rowBase + r1) * Hd + kt + c1 * 8];
            CP_ASYNC16(so + AHI_OFF + SW64((uint32_t)(r0 * 64 + c0 * 16)), s0);
            CP_ASYNC16(so + AHI_OFF + SW64((uint32_t)(r1 * 64 + c1 * 16)), s1);
            const __nv_bfloat16* t0 = &Al[(size_t)(rowBase + r0) * Hd + kt + c0 * 8];
            const __nv_bfloat16* t1 = &Al[(size_t)(rowBase + r1) * Hd + kt + c1 * 8];
            CP_ASYNC16(so + ALO_OFF + SW64((uint32_t)(r0 * 64 + c0 * 16)), t0);
            CP_ASYNC16(so + ALO_OFF + SW64((uint32_t)(r1 * 64 + c1 * 16)), t1);
        }
        // B hi/lo
        {
            const __nv_bfloat16* s0 = &Bh[(size_t)(colBase + r0) * Hd + kt + c0 * 8];
            const __nv_bfloat16* s1 = &Bh[(size_t)(colBase + r1) * Hd + kt + c1 * 8];
            CP_ASYNC16(so + BHI_OFF + SW64((uint32_t)(r0 * 64 + c0 * 16)), s0);
            CP_ASYNC16(so + BHI_OFF + SW64((uint32_t)(r1 * 64 + c1 * 16)), s1);
            const __nv_bfloat16* t0 = &Bl[(size_t)(colBase + r0) * Hd + kt + c0 * 8];
            const __nv_bfloat16* t1 = &Bl[(size_t)(colBase + r1) * Hd + kt + c1 * 8];
            CP_ASYNC16(so + BLO_OFF + SW64((uint32_t)(r0 * 64 + c0 * 16)), t0);
            CP_ASYNC16(so + BLO_OFF + SW64((uint32_t)(r1 * 64 + c1 * 16)), t1);
        }
    };

    float c[4][4][4];
    #pragma unroll
    for (int i = 0; i < 4; i++)
        #pragma unroll
        for (int j = 0; j < 4; j++)
            #pragma unroll
            for (int k = 0; k < 4; k++) c[i][j][k] = 0.0f;

    // ldmatrix per-lane smem offsets (within a stage)
    // A atom ma: row = warpM + ma*16 + (lane&15), colB = (kk + (lane>>4)*8)*2
    const uint32_t a_row = warpM + (lane & 15);
    const uint32_t a_colpart = (lane >> 4) * 16;           // bytes
    // B pair nbp: row = warpN + nbp*16 + ((lane>>4)?8:0) + (lane&7), colB = (kk + ((lane>>3)&1)*8)*2
    const uint32_t b_row = warpN + ((lane >> 4) ? 8u : 0u) + (lane & 7);
    const uint32_t b_colpart = ((lane >> 3) & 1) * 16;     // bytes

    // Prologue: stages 0..2
    load_stage(0); CP_COMMIT();
    load_stage(1); CP_COMMIT();
    load_stage(2); CP_COMMIT();

    for (int ck = 0; ck < NCHUNK; ck++) {
        CP_WAIT2();
        __syncthreads();
        if (ck + 3 < NCHUNK) load_stage(ck + 3);
        CP_COMMIT();                                   // commit every iter (possibly empty)

        const uint32_t so = sb + (ck & 3) * STAGE_BYTES;
        #pragma unroll
        for (int kk = 0; kk < 32; kk += 16) {
            uint32_t ah[4][4], al[4][4], bh[4][2], bl[4][2];
            #pragma unroll
            for (int ma = 0; ma < 4; ma++) {
                uint32_t off = SW64((a_row + ma * 16) * 64 + kk * 2 + a_colpart);
                LDSM_X4(ah[ma][0], ah[ma][1], ah[ma][2], ah[ma][3], so + AHI_OFF + off);
                LDSM_X4(al[ma][0], al[ma][1], al[ma][2], al[ma][3], so + ALO_OFF + off);
            }
            #pragma unroll
            for (int nbp = 0; nbp < 2; nbp++) {
                uint32_t off = SW64((b_row + nbp * 16) * 64 + kk * 2 + b_colpart);
                uint32_t q0, q1, q2, q3;
                LDSM_X4(q0, q1, q2, q3, so + BHI_OFF + off);
                bh[2*nbp][0] = q0; bh[2*nbp][1] = q1; bh[2*nbp+1][0] = q2; bh[2*nbp+1][1] = q3;
                LDSM_X4(q0, q1, q2, q3, so + BLO_OFF + off);
                bl[2*nbp][0] = q0; bl[2*nbp][1] = q1; bl[2*nbp+1][0] = q2; bl[2*nbp+1][1] = q3;
            }
            #pragma unroll
            for (int ma = 0; ma < 4; ma++)
                #pragma unroll
                for (int nb = 0; nb < 4; nb++) {
                    MMA_BF16(c[ma][nb], ah[ma], bh[nb]);
                    MMA_BF16(c[ma][nb], ah[ma], bl[nb]);
                    MMA_BF16(c[ma][nb], al[ma], bh[nb]);
                }
        }
    }
    CP_WAIT0();

    // Epilogue: add bias, write logits
    float bv[8];
    #pragma unroll
    for (int nb = 0; nb < 4; nb++) {
        int cc = colBase + warpN + nb * 8 + (lane & 3) * 2;
        bv[2*nb]   = bias[cc];
        bv[2*nb+1] = bias[cc + 1];
    }
    #pragma unroll
    for (int ma = 0; ma < 4; ma++) {
        int rr0 = rowBase + warpM + ma * 16 + (lane >> 2);
        #pragma unroll
        for (int nb = 0; nb < 4; nb++) {
            int cc = colBase + warpN + nb * 8 + (lane & 3) * 2;
            float2 v0 = make_float2(c[ma][nb][0] + bv[2*nb], c[ma][nb][1] + bv[2*nb+1]);
            float2 v1 = make_float2(c[ma][nb][2] + bv[2*nb], c[ma][nb][3] + bv[2*nb+1]);
            *reinterpret_cast<float2*>(&g_logits[(size_t)rr0 * GVc + cc]) = v0;
            *reinterpret_cast<float2*>(&g_logits[(size_t)(rr0 + 8) * GVc + cc]) = v1;
        }
    }
}

// ---------------------------------------------------------------------------
// Rows: one warp per (n,g): argmax(l+g) gather + masked softmax marginal
// ---------------------------------------------------------------------------
#define RPB 64

__global__ __launch_bounds__(256) void rows_kernel(
    const float* __restrict__ gumbels,
    const int*   __restrict__ mask,
    const float* __restrict__ codevectors,
    float*       __restrict__ out)
{
    __shared__ float sAcc[GVc];
    const int tid = threadIdx.x, lane = tid & 31, warp = tid >> 5;

    for (int i = tid; i < GVc; i += 256) sAcc[i] = 0.0f;
    __syncthreads();

    const int base = blockIdx.x * RPB;
    for (int rr = warp; rr < RPB; rr += 8) {
        const int row = base + rr;
        const int n = row >> 1, g = row & 1;
        const float* lrow = &g_logits[(size_t)n * GVc + g * Vv];
        const float* grow = &gumbels[(size_t)row * Vv];

        float lv[10], ev[10];
        float bestv = -1e30f; int besti = 0; float mx = -1e30f;
        #pragma unroll
        for (int t = 0; t < 10; t++) {
            int v = lane + 32 * t;
            float x = lrow[v];
            lv[t] = x;
            float s = x + grow[v];
            if (s > bestv) { bestv = s; besti = v; }
            mx = fmaxf(mx, x);
        }
        #pragma unroll
        for (int off = 16; off; off >>= 1) {
            float ov = __shfl_xor_sync(0xffffffffu, bestv, off);
            int   oi = __shfl_xor_sync(0xffffffffu, besti, off);
            if (ov > bestv || (ov == bestv && oi < besti)) { bestv = ov; besti = oi; }
            mx = fmaxf(mx, __shfl_xor_sync(0xffffffffu, mx, off));
        }
        float sum = 0.0f;
        #pragma unroll
        for (int t = 0; t < 10; t++) { ev[t] = __expf(lv[t] - mx); sum += ev[t]; }
        #pragma unroll
        for (int off = 16; off; off >>= 1) sum += __shfl_xor_sync(0xffffffffu, sum, off);
        const float inv = 1.0f / sum;

        if (mask[n] != 0) {
            #pragma unroll
            for (int t = 0; t < 10; t++)
                atomicAdd(&sAcc[g * Vv + lane + 32 * t], ev[t] * inv);
        }
        const float4* src = reinterpret_cast<const float4*>(
            &codevectors[((size_t)g * Vv + besti) * (Dd / Gg)]);
        float4* dst = reinterpret_cast<float4*>(&out[(size_t)n * Dd + g * (Dd / Gg)]);
        dst[lane] = src[lane];
    }
    __syncthreads();
    for (int i = tid; i < GVc; i += 256) atomicAdd(&g_acc[i], sAcc[i]);
}

// ---------------------------------------------------------------------------
// Finalize perplexity (640 threads, deterministic)
// ---------------------------------------------------------------------------
__global__ __launch_bounds__(640) void finalize_kernel(float* __restrict__ out, int out_size) {
    __shared__ double wsum[20];
    const int tid = threadIdx.x, lane = tid & 31, warp = tid >> 5;
    const double msum = (double)g_maskcnt;
    double marg = (double)g_acc[tid] / msum;
    double t = marg * log(marg + 1e-7);
    #pragma unroll
    for (int off = 16; off; off >>= 1)
        t += __shfl_xor_sync(0xffffffffu, t, off);
    if (lane == 0) wsum[warp] = t;
    __syncthreads();
    if (tid == 0) {
        double e0 = 0.0, e1 = 0.0;
        for (int w = 0; w < 10; w++)  e0 += wsum[w];
        for (int w = 10; w < 20; w++) e1 += wsum[w];
        out[out_size - 1] = (float)(exp(-e0) + exp(-e1));
    }
}

// ---------------------------------------------------------------------------
extern "C" void kernel_launch(void* const* d_in, const int* in_sizes, int n_in,
                              void* d_out, int out_size)
{
    (void)in_sizes; (void)n_in;
    const float* hs   = (const float*)d_in[0];
    const int*   mask = (const int*)  d_in[1];
    const float* W    = (const float*)d_in[2];
    const float* bias = (const float*)d_in[3];
    const float* cb   = (const float*)d_in[4];
    const float* gmb  = (const float*)d_in[5];
    float* out = (float*)d_out;

    static bool attr_set = false;
    if (!attr_set) {
        cudaFuncSetAttribute(gemm_bf16x3, cudaFuncAttributeMaxDynamicSharedMemorySize, GEMM_SMEM);
        attr_set = true;
    }

    prep_W<<<(Hd * GVc) / 256, 256>>>(W);
    prep_A<<<(Nrows * Hd / 4) / 256, 256>>>(hs);
    mask_kernel<<<Nrows / 1024, 256>>>(mask);

    dim3 ggrid(GVc / 128, Nrows / 128);   // (5, 128)
    gemm_bf16x3<<<ggrid, 256, GEMM_SMEM>>>(bias);

    rows_kernel<<<(Nrows * Gg) / RPB, 256>>>(gmb, mask, cb, out);
    finalize_kernel<<<1, 640>>>(out, out_size);
}

// round 4
// speedup vs baseline: 2.1498x; 1.0520x over previous
#include <cuda_runtime.h>
#include <cuda_bf16.h>
#include <cstdint>

// Problem shapes
#define Nrows 16384
#define Hd    512
#define Gg    2
#define Vv    320
#define Dd    256
#define GVc   640

// ---------------------------------------------------------------------------
// Device scratch
// ---------------------------------------------------------------------------
__device__ float g_logits[(size_t)Nrows * GVc];                 // 41.9 MB
__device__ __nv_bfloat16 g_A_hi[(size_t)Nrows * Hd];            // 16.8 MB
__device__ __nv_bfloat16 g_A_lo[(size_t)Nrows * Hd];            // 16.8 MB
__device__ __nv_bfloat16 g_Wt_hi[(size_t)GVc * Hd];             // 0.65 MB
__device__ __nv_bfloat16 g_Wt_lo[(size_t)GVc * Hd];
__device__ float g_acc[GVc];
__device__ float g_maskcnt;

// ---------------------------------------------------------------------------
// Helpers (baseline ISA only)
// ---------------------------------------------------------------------------
__device__ __forceinline__ uint32_t smem_u32(const void* p) {
    uint32_t a;
    asm("{ .reg .u64 t; cvta.to.shared.u64 t, %1; cvt.u32.u64 %0, t; }" : "=r"(a) : "l"(p));
    return a;
}
#define CP_ASYNC16(dst, src) \
    asm volatile("cp.async.cg.shared.global [%0], [%1], 16;" :: "r"(dst), "l"(src) : "memory")
#define CP_COMMIT() asm volatile("cp.async.commit_group;" ::: "memory")
#define CP_WAIT2()  asm volatile("cp.async.wait_group 2;" ::: "memory")
#define CP_WAIT0()  asm volatile("cp.async.wait_group 0;" ::: "memory")

#define LDSM_X4(r0, r1, r2, r3, a) \
    asm volatile("ldmatrix.sync.aligned.m8n8.x4.shared.b16 {%0,%1,%2,%3}, [%4];" \
        : "=r"(r0), "=r"(r1), "=r"(r2), "=r"(r3) : "r"(a))

#define MMA_BF16(c, a, b) \
    asm volatile("mma.sync.aligned.m16n8k16.row.col.f32.bf16.bf16.f32 " \
        "{%0,%1,%2,%3}, {%4,%5,%6,%7}, {%8,%9}, {%0,%1,%2,%3};" \
        : "+f"((c)[0]), "+f"((c)[1]), "+f"((c)[2]), "+f"((c)[3]) \
        : "r"((a)[0]), "r"((a)[1]), "r"((a)[2]), "r"((a)[3]), "r"((b)[0]), "r"((b)[1]))

#define SW64(o) ((o) ^ (((o) >> 3) & 0x30))

// ---------------------------------------------------------------------------
// Prep kernels
// ---------------------------------------------------------------------------
__global__ __launch_bounds__(256) void prep_W(const float* __restrict__ W) {
    int idx = blockIdx.x * 256 + threadIdx.x;        // 0..327679
    if (idx < GVc) g_acc[idx] = 0.0f;
    if (idx == 0) g_maskcnt = 0.0f;
    float x = W[idx];
    int k = idx / GVc, n = idx % GVc;
    __nv_bfloat16 h = __float2bfloat16_rn(x);
    float r = x - __bfloat162float(h);
    g_Wt_hi[(size_t)n * Hd + k] = h;
    g_Wt_lo[(size_t)n * Hd + k] = __float2bfloat16_rn(r);
}

__global__ __launch_bounds__(256) void prep_A(const float* __restrict__ A) {
    size_t idx = (size_t)blockIdx.x * 256 + threadIdx.x;   // over float4's
    float4 v = reinterpret_cast<const float4*>(A)[idx];
    __nv_bfloat16 h0 = __float2bfloat16_rn(v.x), h1 = __float2bfloat16_rn(v.y);
    __nv_bfloat16 h2 = __float2bfloat16_rn(v.z), h3 = __float2bfloat16_rn(v.w);
    __nv_bfloat162 hi01; hi01.x = h0; hi01.y = h1;
    __nv_bfloat162 hi23; hi23.x = h2; hi23.y = h3;
    __nv_bfloat162 lo01, lo23;
    lo01.x = __float2bfloat16_rn(v.x - __bfloat162float(h0));
    lo01.y = __float2bfloat16_rn(v.y - __bfloat162float(h1));
    lo23.x = __float2bfloat16_rn(v.z - __bfloat162float(h2));
    lo23.y = __float2bfloat16_rn(v.w - __bfloat162float(h3));
    reinterpret_cast<__nv_bfloat162*>(g_A_hi)[idx * 2 + 0] = hi01;
    reinterpret_cast<__nv_bfloat162*>(g_A_hi)[idx * 2 + 1] = hi23;
    reinterpret_cast<__nv_bfloat162*>(g_A_lo)[idx * 2 + 0] = lo01;
    reinterpret_cast<__nv_bfloat162*>(g_A_lo)[idx * 2 + 1] = lo23;
}

__global__ __launch_bounds__(256) void mask_kernel(const int* __restrict__ mask) {
    __shared__ float red[256];
    int tid = threadIdx.x;
    int4 m = reinterpret_cast<const int4*>(mask)[blockIdx.x * 256 + tid];
    float c = (m.x != 0) + (m.y != 0) + (m.z != 0) + (m.w != 0);
    red[tid] = c; __syncthreads();
    for (int s = 128; s > 0; s >>= 1) { if (tid < s) red[tid] += red[tid + s]; __syncthreads(); }
    if (tid == 0) atomicAdd(&g_maskcnt, red[0]);
}

// ---------------------------------------------------------------------------
// bf16x3 GEMM: logits[16384,640] = A @ W + bias
// 128x64 CTA tile, BK=32, 4-stage cp.async, SW64 swizzle, 2 CTAs/SM.
// Warps 2(M)x4(N): warp tile 64x16 -> c[4][2][4].
// ---------------------------------------------------------------------------
#define NSTAGE 4
#define NCHUNK 16
#define STAGE_BYTES 24576
#define AHI_OFF 0
#define ALO_OFF 8192
#define BHI_OFF 16384
#define BLO_OFF 20480
#define GEMM_SMEM (NSTAGE * STAGE_BYTES + 1024)

__global__ __launch_bounds__(256, 2) void gemm_bf16x3(const float* __restrict__ bias) {
    extern __shared__ char dsm[];
    const uint32_t raw = smem_u32(dsm);
    const uint32_t sb = (raw + 1023u) & ~1023u;

    const int tid = threadIdx.x;
    const int wid = tid >> 5, lane = tid & 31;
    const int rowBase = blockIdx.y * 128;
    const int colBase = blockIdx.x * 64;
    const int warpM = (wid & 1) * 64;        // 2 warps over M=128
    const int warpN = (wid >> 1) * 16;       // 4 warps over N=64

    const __nv_bfloat16* __restrict__ Ah = g_A_hi;
    const __nv_bfloat16* __restrict__ Al = g_A_lo;
    const __nv_bfloat16* __restrict__ Bh = g_Wt_hi;
    const __nv_bfloat16* __restrict__ Bl = g_Wt_lo;

    // load coords: A 128x32 (512 chunks -> 2/thread), B 64x32 (256 -> 1/thread)
    const int ra0 = tid >> 2,          ca = tid & 3;
    const int ra1 = (tid + 256) >> 2;
    const int rb  = tid >> 2;

    auto load_stage = [&](int ck) {
        const uint32_t so = sb + (ck & 3) * STAGE_BYTES;
        const int kt = ck * 32;
        const uint32_t offA0 = SW64((uint32_t)(ra0 * 64 + ca * 16));
        const uint32_t offA1 = SW64((uint32_t)(ra1 * 64 + ca * 16));
        const uint32_t offB  = SW64((uint32_t)(rb  * 64 + ca * 16));
        CP_ASYNC16(so + AHI_OFF + offA0, &Ah[(size_t)(rowBase + ra0) * Hd + kt + ca * 8]);
        CP_ASYNC16(so + AHI_OFF + offA1, &Ah[(size_t)(rowBase + ra1) * Hd + kt + ca * 8]);
        CP_ASYNC16(so + ALO_OFF + offA0, &Al[(size_t)(rowBase + ra0) * Hd + kt + ca * 8]);
        CP_ASYNC16(so + ALO_OFF + offA1, &Al[(size_t)(rowBase + ra1) * Hd + kt + ca * 8]);
        CP_ASYNC16(so + BHI_OFF + offB,  &Bh[(size_t)(colBase + rb) * Hd + kt + ca * 8]);
        CP_ASYNC16(so + BLO_OFF + offB,  &Bl[(size_t)(colBase + rb) * Hd + kt + ca * 8]);
    };

    float c[4][2][4];
    #pragma unroll
    for (int i = 0; i < 4; i++)
        #pragma unroll
        for (int j = 0; j < 2; j++)
            #pragma unroll
            for (int k = 0; k < 4; k++) c[i][j][k] = 0.0f;

    const uint32_t a_row = warpM + (lane & 15);
    const uint32_t a_colpart = (lane >> 4) * 16;
    const uint32_t b_row = warpN + ((lane >> 4) ? 8u : 0u) + (lane & 7);
    const uint32_t b_colpart = ((lane >> 3) & 1) * 16;

    load_stage(0); CP_COMMIT();
    load_stage(1); CP_COMMIT();
    load_stage(2); CP_COMMIT();

    for (int ck = 0; ck < NCHUNK; ck++) {
        CP_WAIT2();
        __syncthreads();
        if (ck + 3 < NCHUNK) load_stage(ck + 3);
        CP_COMMIT();

        const uint32_t so = sb + (ck & 3) * STAGE_BYTES;
        #pragma unroll
        for (int kk = 0; kk < 32; kk += 16) {
            uint32_t ah[4][4], al[4][4], bh[2][2], bl[2][2];
            #pragma unroll
            for (int ma = 0; ma < 4; ma++) {
                uint32_t off = SW64((a_row + ma * 16) * 64 + kk * 2 + a_colpart);
                LDSM_X4(ah[ma][0], ah[ma][1], ah[ma][2], ah[ma][3], so + AHI_OFF + off);
                LDSM_X4(al[ma][0], al[ma][1], al[ma][2], al[ma][3], so + ALO_OFF + off);
            }
            {
                uint32_t off = SW64(b_row * 64 + kk * 2 + b_colpart);
                uint32_t q0, q1, q2, q3;
                LDSM_X4(q0, q1, q2, q3, so + BHI_OFF + off);
                bh[0][0] = q0; bh[0][1] = q1; bh[1][0] = q2; bh[1][1] = q3;
                LDSM_X4(q0, q1, q2, q3, so + BLO_OFF + off);
                bl[0][0] = q0; bl[0][1] = q1; bl[1][0] = q2; bl[1][1] = q3;
            }
            // pass-ordered: independence distance = 8 MMAs
            #pragma unroll
            for (int ma = 0; ma < 4; ma++)
                #pragma unroll
                for (int nb = 0; nb < 2; nb++) MMA_BF16(c[ma][nb], ah[ma], bh[nb]);
            #pragma unroll
            for (int ma = 0; ma < 4; ma++)
                #pragma unroll
                for (int nb = 0; nb < 2; nb++) MMA_BF16(c[ma][nb], al[ma], bh[nb]);
            #pragma unroll
            for (int ma = 0; ma < 4; ma++)
                #pragma unroll
                for (int nb = 0; nb < 2; nb++) MMA_BF16(c[ma][nb], ah[ma], bl[nb]);
        }
    }
    CP_WAIT0();

    // Epilogue
    float bv[4];
    #pragma unroll
    for (int nb = 0; nb < 2; nb++) {
        int cc = colBase + warpN + nb * 8 + (lane & 3) * 2;
        bv[2*nb]   = bias[cc];
        bv[2*nb+1] = bias[cc + 1];
    }
    #pragma unroll
    for (int ma = 0; ma < 4; ma++) {
        int rr0 = rowBase + warpM + ma * 16 + (lane >> 2);
        #pragma unroll
        for (int nb = 0; nb < 2; nb++) {
            int cc = colBase + warpN + nb * 8 + (lane & 3) * 2;
            float2 v0 = make_float2(c[ma][nb][0] + bv[2*nb], c[ma][nb][1] + bv[2*nb+1]);
            float2 v1 = make_float2(c[ma][nb][2] + bv[2*nb], c[ma][nb][3] + bv[2*nb+1]);
            *reinterpret_cast<float2*>(&g_logits[(size_t)rr0 * GVc + cc]) = v0;
            *reinterpret_cast<float2*>(&g_logits[(size_t)(rr0 + 8) * GVc + cc]) = v1;
        }
    }
}

// ---------------------------------------------------------------------------
// Rows: one warp per (n,g): argmax(l+g) gather + masked softmax marginal
// ---------------------------------------------------------------------------
#define RPB 64

__global__ __launch_bounds__(256) void rows_kernel(
    const float* __restrict__ gumbels,
    const int*   __restrict__ mask,
    const float* __restrict__ codevectors,
    float*       __restrict__ out)
{
    __shared__ float sAcc[GVc];
    const int tid = threadIdx.x, lane = tid & 31, warp = tid >> 5;

    for (int i = tid; i < GVc; i += 256) sAcc[i] = 0.0f;
    __syncthreads();

    const int base = blockIdx.x * RPB;
    for (int rr = warp; rr < RPB; rr += 8) {
        const int row = base + rr;
        const int n = row >> 1, g = row & 1;
        const float* lrow = &g_logits[(size_t)n * GVc + g * Vv];
        const float* grow = &gumbels[(size_t)row * Vv];

        float lv[10], ev[10];
        float bestv = -1e30f; int besti = 0; float mx = -1e30f;
        #pragma unroll
        for (int t = 0; t < 10; t++) {
            int v = lane + 32 * t;
            float x = lrow[v];
            lv[t] = x;
            float s = x + grow[v];
            if (s > bestv) { bestv = s; besti = v; }
            mx = fmaxf(mx, x);
        }
        #pragma unroll
        for (int off = 16; off; off >>= 1) {
            float ov = __shfl_xor_sync(0xffffffffu, bestv, off);
            int   oi = __shfl_xor_sync(0xffffffffu, besti, off);
            if (ov > bestv || (ov == bestv && oi < besti)) { bestv = ov; besti = oi; }
            mx = fmaxf(mx, __shfl_xor_sync(0xffffffffu, mx, off));
        }
        float sum = 0.0f;
        #pragma unroll
        for (int t = 0; t < 10; t++) { ev[t] = __expf(lv[t] - mx); sum += ev[t]; }
        #pragma unroll
        for (int off = 16; off; off >>= 1) sum += __shfl_xor_sync(0xffffffffu, sum, off);
        const float inv = 1.0f / sum;

        if (mask[n] != 0) {
            #pragma unroll
            for (int t = 0; t < 10; t++)
                atomicAdd(&sAcc[g * Vv + lane + 32 * t], ev[t] * inv);
        }
        const float4* src = reinterpret_cast<const float4*>(
            &codevectors[((size_t)g * Vv + besti) * (Dd / Gg)]);
        float4* dst = reinterpret_cast<float4*>(&out[(size_t)n * Dd + g * (Dd / Gg)]);
        dst[lane] = src[lane];
    }
    __syncthreads();
    for (int i = tid; i < GVc; i += 256) atomicAdd(&g_acc[i], sAcc[i]);
}

// ---------------------------------------------------------------------------
// Finalize perplexity
// ---------------------------------------------------------------------------
__global__ __launch_bounds__(640) void finalize_kernel(float* __restrict__ out, int out_size) {
    __shared__ double wsum[20];
    const int tid = threadIdx.x, lane = tid & 31, warp = tid >> 5;
    const double msum = (double)g_maskcnt;
    double marg = (double)g_acc[tid] / msum;
    double t = marg * log(marg + 1e-7);
    #pragma unroll
    for (int off = 16; off; off >>= 1)
        t += __shfl_xor_sync(0xffffffffu, t, off);
    if (lane == 0) wsum[warp] = t;
    __syncthreads();
    if (tid == 0) {
        double e0 = 0.0, e1 = 0.0;
        for (int w = 0; w < 10; w++)  e0 += wsum[w];
        for (int w = 10; w < 20; w++) e1 += wsum[w];
        out[out_size - 1] = (float)(exp(-e0) + exp(-e1));
    }
}

// ---------------------------------------------------------------------------
extern "C" void kernel_launch(void* const* d_in, const int* in_sizes, int n_in,
                              void* d_out, int out_size)
{
    (void)in_sizes; (void)n_in;
    const float* hs   = (const float*)d_in[0];
    const int*   mask = (const int*)  d_in[1];
    const float* W    = (const float*)d_in[2];
    const float* bias = (const float*)d_in[3];
    const float* cb   = (const float*)d_in[4];
    const float* gmb  = (const float*)d_in[5];
    float* out = (float*)d_out;

    static bool attr_set = false;
    if (!attr_set) {
        cudaFuncSetAttribute(gemm_bf16x3, cudaFuncAttributeMaxDynamicSharedMemorySize, GEMM_SMEM);
        attr_set = true;
    }

    prep_W<<<(Hd * GVc) / 256, 256>>>(W);
    prep_A<<<(Nrows * Hd / 4) / 256, 256>>>(hs);
    mask_kernel<<<Nrows / 1024, 256>>>(mask);

    dim3 ggrid(GVc / 64, Nrows / 128);   // (10, 128) = 1280 CTAs
    gemm_bf16x3<<<ggrid, 256, GEMM_SMEM>>>(bias);

    rows_kernel<<<(Nrows * Gg) / RPB, 256>>>(gmb, mask, cb, out);
    finalize_kernel<<<1, 640>>>(out, out_size);
}

// round 5
// speedup vs baseline: 2.2449x; 1.0442x over previous
#include <cuda_runtime.h>
#include <cuda_bf16.h>
#include <cstdint>

// Problem shapes
#define Nrows 16384
#define Hd    512
#define Gg    2
#define Vv    320
#define Dd    256
#define GVc   640

// ---------------------------------------------------------------------------
// Device scratch
// ---------------------------------------------------------------------------
__device__ float g_logits[(size_t)Nrows * GVc];                 // 41.9 MB
__device__ __nv_bfloat16 g_A_hi[(size_t)Nrows * Hd];            // 16.8 MB
__device__ __nv_bfloat16 g_A_lo[(size_t)Nrows * Hd];            // 16.8 MB
__device__ __nv_bfloat16 g_Wt_hi[(size_t)GVc * Hd];             // 0.65 MB
__device__ __nv_bfloat16 g_Wt_lo[(size_t)GVc * Hd];
__device__ float g_acc[GVc];
__device__ float g_maskcnt;

// ---------------------------------------------------------------------------
// Helpers (baseline ISA only)
// ---------------------------------------------------------------------------
__device__ __forceinline__ uint32_t smem_u32(const void* p) {
    uint32_t a;
    asm("{ .reg .u64 t; cvta.to.shared.u64 t, %1; cvt.u32.u64 %0, t; }" : "=r"(a) : "l"(p));
    return a;
}
#define CP_ASYNC16(dst, src) \
    asm volatile("cp.async.cg.shared.global [%0], [%1], 16;" :: "r"(dst), "l"(src) : "memory")
#define CP_COMMIT() asm volatile("cp.async.commit_group;" ::: "memory")
#define CP_WAIT2()  asm volatile("cp.async.wait_group 2;" ::: "memory")
#define CP_WAIT0()  asm volatile("cp.async.wait_group 0;" ::: "memory")

#define LDSM_X4(r0, r1, r2, r3, a) \
    asm volatile("ldmatrix.sync.aligned.m8n8.x4.shared.b16 {%0,%1,%2,%3}, [%4];" \
        : "=r"(r0), "=r"(r1), "=r"(r2), "=r"(r3) : "r"(a))

#define MMA_BF16(c, a, b) \
    asm volatile("mma.sync.aligned.m16n8k16.row.col.f32.bf16.bf16.f32 " \
        "{%0,%1,%2,%3}, {%4,%5,%6,%7}, {%8,%9}, {%0,%1,%2,%3};" \
        : "+f"((c)[0]), "+f"((c)[1]), "+f"((c)[2]), "+f"((c)[3]) \
        : "r"((a)[0]), "r"((a)[1]), "r"((a)[2]), "r"((a)[3]), "r"((b)[0]), "r"((b)[1]))

#define SW64(o) ((o) ^ (((o) >> 3) & 0x30))

// ---------------------------------------------------------------------------
// Prep kernels
// ---------------------------------------------------------------------------
__global__ __launch_bounds__(256) void prep_W(const float* __restrict__ W) {
    int idx = blockIdx.x * 256 + threadIdx.x;        // 0..327679
    if (idx < GVc) g_acc[idx] = 0.0f;
    if (idx == 0) g_maskcnt = 0.0f;
    float x = W[idx];
    int k = idx / GVc, n = idx % GVc;
    __nv_bfloat16 h = __float2bfloat16_rn(x);
    float r = x - __bfloat162float(h);
    g_Wt_hi[(size_t)n * Hd + k] = h;
    g_Wt_lo[(size_t)n * Hd + k] = __float2bfloat16_rn(r);
}

__global__ __launch_bounds__(256) void prep_A(const float* __restrict__ A) {
    size_t idx = (size_t)blockIdx.x * 256 + threadIdx.x;   // over float4's
    float4 v = reinterpret_cast<const float4*>(A)[idx];
    __nv_bfloat16 h0 = __float2bfloat16_rn(v.x), h1 = __float2bfloat16_rn(v.y);
    __nv_bfloat16 h2 = __float2bfloat16_rn(v.z), h3 = __float2bfloat16_rn(v.w);
    __nv_bfloat162 hi01; hi01.x = h0; hi01.y = h1;
    __nv_bfloat162 hi23; hi23.x = h2; hi23.y = h3;
    __nv_bfloat162 lo01, lo23;
    lo01.x = __float2bfloat16_rn(v.x - __bfloat162float(h0));
    lo01.y = __float2bfloat16_rn(v.y - __bfloat162float(h1));
    lo23.x = __float2bfloat16_rn(v.z - __bfloat162float(h2));
    lo23.y = __float2bfloat16_rn(v.w - __bfloat162float(h3));
    reinterpret_cast<__nv_bfloat162*>(g_A_hi)[idx * 2 + 0] = hi01;
    reinterpret_cast<__nv_bfloat162*>(g_A_hi)[idx * 2 + 1] = hi23;
    reinterpret_cast<__nv_bfloat162*>(g_A_lo)[idx * 2 + 0] = lo01;
    reinterpret_cast<__nv_bfloat162*>(g_A_lo)[idx * 2 + 1] = lo23;
}

__global__ __launch_bounds__(256) void mask_kernel(const int* __restrict__ mask) {
    __shared__ float red[256];
    int tid = threadIdx.x;
    int4 m = reinterpret_cast<const int4*>(mask)[blockIdx.x * 256 + tid];
    float c = (m.x != 0) + (m.y != 0) + (m.z != 0) + (m.w != 0);
    red[tid] = c; __syncthreads();
    for (int s = 128; s > 0; s >>= 1) { if (tid < s) red[tid] += red[tid + s]; __syncthreads(); }
    if (tid == 0) atomicAdd(&g_maskcnt, red[0]);
}

// ---------------------------------------------------------------------------
// bf16x3 GEMM: logits[16384,640] = A @ W + bias
// 128x64 CTA tile, BK=32, 4-stage cp.async, SW64 swizzle, 2 CTAs/SM.
// Warps 4(M)x2(N): warp tile 32x32 -> c[2][4][4]. Interleaved LDSM/MMA.
// ---------------------------------------------------------------------------
#define NSTAGE 4
#define NCHUNK 16
#define STAGE_BYTES 24576
#define AHI_OFF 0
#define ALO_OFF 8192
#define BHI_OFF 16384
#define BLO_OFF 20480
#define GEMM_SMEM (NSTAGE * STAGE_BYTES + 1024)

__global__ __launch_bounds__(256, 2) void gemm_bf16x3(const float* __restrict__ bias) {
    extern __shared__ char dsm[];
    const uint32_t raw = smem_u32(dsm);
    const uint32_t sb = (raw + 1023u) & ~1023u;

    const int tid = threadIdx.x;
    const int wid = tid >> 5, lane = tid & 31;
    const int rowBase = blockIdx.y * 128;
    const int colBase = blockIdx.x * 64;
    const int warpM = (wid & 3) * 32;        // 4 warps over M=128
    const int warpN = (wid >> 2) * 32;       // 2 warps over N=64

    const __nv_bfloat16* __restrict__ Ah = g_A_hi;
    const __nv_bfloat16* __restrict__ Al = g_A_lo;
    const __nv_bfloat16* __restrict__ Bh = g_Wt_hi;
    const __nv_bfloat16* __restrict__ Bl = g_Wt_lo;

    // load coords: A 128x32 (512 chunks -> 2/thread), B 64x32 (256 -> 1/thread)
    const int ra0 = tid >> 2,          ca = tid & 3;
    const int ra1 = (tid + 256) >> 2;
    const int rb  = tid >> 2;

    auto load_stage = [&](int ck) {
        const uint32_t so = sb + (ck & 3) * STAGE_BYTES;
        const int kt = ck * 32;
        const uint32_t offA0 = SW64((uint32_t)(ra0 * 64 + ca * 16));
        const uint32_t offA1 = SW64((uint32_t)(ra1 * 64 + ca * 16));
        const uint32_t offB  = SW64((uint32_t)(rb  * 64 + ca * 16));
        CP_ASYNC16(so + AHI_OFF + offA0, &Ah[(size_t)(rowBase + ra0) * Hd + kt + ca * 8]);
        CP_ASYNC16(so + AHI_OFF + offA1, &Ah[(size_t)(rowBase + ra1) * Hd + kt + ca * 8]);
        CP_ASYNC16(so + ALO_OFF + offA0, &Al[(size_t)(rowBase + ra0) * Hd + kt + ca * 8]);
        CP_ASYNC16(so + ALO_OFF + offA1, &Al[(size_t)(rowBase + ra1) * Hd + kt + ca * 8]);
        CP_ASYNC16(so + BHI_OFF + offB,  &Bh[(size_t)(colBase + rb) * Hd + kt + ca * 8]);
        CP_ASYNC16(so + BLO_OFF + offB,  &Bl[(size_t)(colBase + rb) * Hd + kt + ca * 8]);
    };

    float c[2][4][4];
    #pragma unroll
    for (int i = 0; i < 2; i++)
        #pragma unroll
        for (int j = 0; j < 4; j++)
            #pragma unroll
            for (int k = 0; k < 4; k++) c[i][j][k] = 0.0f;

    const uint32_t a_row = warpM + (lane & 15);
    const uint32_t a_colpart = (lane >> 4) * 16;
    const uint32_t b_row = warpN + ((lane >> 4) ? 8u : 0u) + (lane & 7);
    const uint32_t b_colpart = ((lane >> 3) & 1) * 16;

    load_stage(0); CP_COMMIT();
    load_stage(1); CP_COMMIT();
    load_stage(2); CP_COMMIT();

    for (int ck = 0; ck < NCHUNK; ck++) {
        CP_WAIT2();
        __syncthreads();
        if (ck + 3 < NCHUNK) load_stage(ck + 3);
        CP_COMMIT();

        const uint32_t so = sb + (ck & 3) * STAGE_BYTES;
        #pragma unroll
        for (int kk = 0; kk < 32; kk += 16) {
            uint32_t ah[2][4], al[2][4], bh[4][2], bl[4][2];
            uint32_t aoff[2], boff[2];
            #pragma unroll
            for (int ma = 0; ma < 2; ma++)
                aoff[ma] = SW64((a_row + ma * 16) * 64 + kk * 2 + a_colpart);
            #pragma unroll
            for (int p = 0; p < 2; p++)
                boff[p] = SW64((b_row + p * 16) * 64 + kk * 2 + b_colpart);

            // --- group 1: bh + ah, then hh MMAs ---
            #pragma unroll
            for (int p = 0; p < 2; p++) {
                uint32_t q0, q1, q2, q3;
                LDSM_X4(q0, q1, q2, q3, so + BHI_OFF + boff[p]);
                bh[2*p][0] = q0; bh[2*p][1] = q1; bh[2*p+1][0] = q2; bh[2*p+1][1] = q3;
            }
            #pragma unroll
            for (int ma = 0; ma < 2; ma++)
                LDSM_X4(ah[ma][0], ah[ma][1], ah[ma][2], ah[ma][3], so + AHI_OFF + aoff[ma]);
            #pragma unroll
            for (int ma = 0; ma < 2; ma++)
                #pragma unroll
                for (int nb = 0; nb < 4; nb++) MMA_BF16(c[ma][nb], ah[ma], bh[nb]);

            // --- group 2: al, then lh MMAs ---
            #pragma unroll
            for (int ma = 0; ma < 2; ma++)
                LDSM_X4(al[ma][0], al[ma][1], al[ma][2], al[ma][3], so + ALO_OFF + aoff[ma]);
            #pragma unroll
            for (int ma = 0; ma < 2; ma++)
                #pragma unroll
                for (int nb = 0; nb < 4; nb++) MMA_BF16(c[ma][nb], al[ma], bh[nb]);

            // --- group 3: bl, then hl MMAs ---
            #pragma unroll
            for (int p = 0; p < 2; p++) {
                uint32_t q0, q1, q2, q3;
                LDSM_X4(q0, q1, q2, q3, so + BLO_OFF + boff[p]);
                bl[2*p][0] = q0; bl[2*p][1] = q1; bl[2*p+1][0] = q2; bl[2*p+1][1] = q3;
            }
            #pragma unroll
            for (int ma = 0; ma < 2; ma++)
                #pragma unroll
                for (int nb = 0; nb < 4; nb++) MMA_BF16(c[ma][nb], ah[ma], bl[nb]);
        }
    }
    CP_WAIT0();

    // Epilogue
    float bv[8];
    #pragma unroll
    for (int nb = 0; nb < 4; nb++) {
        int cc = colBase + warpN + nb * 8 + (lane & 3) * 2;
        bv[2*nb]   = bias[cc];
        bv[2*nb+1] = bias[cc + 1];
    }
    #pragma unroll
    for (int ma = 0; ma < 2; ma++) {
        int rr0 = rowBase + warpM + ma * 16 + (lane >> 2);
        #pragma unroll
        for (int nb = 0; nb < 4; nb++) {
            int cc = colBase + warpN + nb * 8 + (lane & 3) * 2;
            float2 v0 = make_float2(c[ma][nb][0] + bv[2*nb], c[ma][nb][1] + bv[2*nb+1]);
            float2 v1 = make_float2(c[ma][nb][2] + bv[2*nb], c[ma][nb][3] + bv[2*nb+1]);
            *reinterpret_cast<float2*>(&g_logits[(size_t)rr0 * GVc + cc]) = v0;
            *reinterpret_cast<float2*>(&g_logits[(size_t)(rr0 + 8) * GVc + cc]) = v1;
        }
    }
}

// ---------------------------------------------------------------------------
// Rows: one warp per (n,g): argmax(l+g) gather + masked softmax marginal
// ---------------------------------------------------------------------------
#define RPB 64

__global__ __launch_bounds__(256) void rows_kernel(
    const float* __restrict__ gumbels,
    const int*   __restrict__ mask,
    const float* __restrict__ codevectors,
    float*       __restrict__ out)
{
    __shared__ float sAcc[GVc];
    const int tid = threadIdx.x, lane = tid & 31, warp = tid >> 5;

    for (int i = tid; i < GVc; i += 256) sAcc[i] = 0.0f;
    __syncthreads();

    const int base = blockIdx.x * RPB;
    for (int rr = warp; rr < RPB; rr += 8) {
        const int row = base + rr;
        const int n = row >> 1, g = row & 1;
        const float* lrow = &g_logits[(size_t)n * GVc + g * Vv];
        const float* grow = &gumbels[(size_t)row * Vv];

        float lv[10], ev[10];
        float bestv = -1e30f; int besti = 0; float mx = -1e30f;
        #pragma unroll
        for (int t = 0; t < 10; t++) {
            int v = lane + 32 * t;
            float x = lrow[v];
            lv[t] = x;
            float s = x + grow[v];
            if (s > bestv) { bestv = s; besti = v; }
            mx = fmaxf(mx, x);
        }
        #pragma unroll
        for (int off = 16; off; off >>= 1) {
            float ov = __shfl_xor_sync(0xffffffffu, bestv, off);
            int   oi = __shfl_xor_sync(0xffffffffu, besti, off);
            if (ov > bestv || (ov == bestv && oi < besti)) { bestv = ov; besti = oi; }
            mx = fmaxf(mx, __shfl_xor_sync(0xffffffffu, mx, off));
        }
        float sum = 0.0f;
        #pragma unroll
        for (int t = 0; t < 10; t++) { ev[t] = __expf(lv[t] - mx); sum += ev[t]; }
        #pragma unroll
        for (int off = 16; off; off >>= 1) sum += __shfl_xor_sync(0xffffffffu, sum, off);
        const float inv = 1.0f / sum;

        if (mask[n] != 0) {
            #pragma unroll
            for (int t = 0; t < 10; t++)
                atomicAdd(&sAcc[g * Vv + lane + 32 * t], ev[t] * inv);
        }
        const float4* src = reinterpret_cast<const float4*>(
            &codevectors[((size_t)g * Vv + besti) * (Dd / Gg)]);
        float4* dst = reinterpret_cast<float4*>(&out[(size_t)n * Dd + g * (Dd / Gg)]);
        dst[lane] = src[lane];
    }
    __syncthreads();
    for (int i = tid; i < GVc; i += 256) atomicAdd(&g_acc[i], sAcc[i]);
}

// ---------------------------------------------------------------------------
// Finalize perplexity
// ---------------------------------------------------------------------------
__global__ __launch_bounds__(640) void finalize_kernel(float* __restrict__ out, int out_size) {
    __shared__ double wsum[20];
    const int tid = threadIdx.x, lane = tid & 31, warp = tid >> 5;
    const double msum = (double)g_maskcnt;
    double marg = (double)g_acc[tid] / msum;
    double t = marg * log(marg + 1e-7);
    #pragma unroll
    for (int off = 16; off; off >>= 1)
        t += __shfl_xor_sync(0xffffffffu, t, off);
    if (lane == 0) wsum[warp] = t;
    __syncthreads();
    if (tid == 0) {
        double e0 = 0.0, e1 = 0.0;
        for (int w = 0; w < 10; w++)  e0 += wsum[w];
        for (int w = 10; w < 20; w++) e1 += wsum[w];
        out[out_size - 1] = (float)(exp(-e0) + exp(-e1));
    }
}

// ---------------------------------------------------------------------------
extern "C" void kernel_launch(void* const* d_in, const int* in_sizes, int n_in,
                              void* d_out, int out_size)
{
    (void)in_sizes; (void)n_in;
    const float* hs   = (const float*)d_in[0];
    const int*   mask = (const int*)  d_in[1];
    const float* W    = (const float*)d_in[2];
    const float* bias = (const float*)d_in[3];
    const float* cb   = (const float*)d_in[4];
    const float* gmb  = (const float*)d_in[5];
    float* out = (float*)d_out;

    static bool attr_set = false;
    if (!attr_set) {
        cudaFuncSetAttribute(gemm_bf16x3, cudaFuncAttributeMaxDynamicSharedMemorySize, GEMM_SMEM);
        attr_set = true;
    }

    prep_W<<<(Hd * GVc) / 256, 256>>>(W);
    prep_A<<<(Nrows * Hd / 4) / 256, 256>>>(hs);
    mask_kernel<<<Nrows / 1024, 256>>>(mask);

    dim3 ggrid(GVc / 64, Nrows / 128);   // (10, 128) = 1280 CTAs
    gemm_bf16x3<<<ggrid, 256, GEMM_SMEM>>>(bias);

    rows_kernel<<<(Nrows * Gg) / RPB, 256>>>(gmb, mask, cb, out);
    finalize_kernel<<<1, 640>>>(out, out_size);
}

// round 6
// speedup vs baseline: 2.2769x; 1.0143x over previous
#include <cuda_runtime.h>
#include <cuda_bf16.h>
#include <cstdint>

// Problem shapes
#define Nrows 16384
#define Hd    512
#define Gg    2
#define Vv    320
#define Dd    256
#define GVc   640

// ---------------------------------------------------------------------------
// Device scratch
// ---------------------------------------------------------------------------
__device__ float g_logits[(size_t)Nrows * GVc];                 // 41.9 MB
__device__ __nv_bfloat16 g_A_hi[(size_t)Nrows * Hd];            // 16.8 MB
__device__ __nv_bfloat16 g_A_lo[(size_t)Nrows * Hd];            // 16.8 MB
__device__ __nv_bfloat16 g_Wt_hi[(size_t)GVc * Hd];             // 0.65 MB
__device__ __nv_bfloat16 g_Wt_lo[(size_t)GVc * Hd];
__device__ float g_acc[GVc];

// ---------------------------------------------------------------------------
// Helpers (baseline ISA only)
// ---------------------------------------------------------------------------
__device__ __forceinline__ uint32_t smem_u32(const void* p) {
    uint32_t a;
    asm("{ .reg .u64 t; cvta.to.shared.u64 t, %1; cvt.u32.u64 %0, t; }" : "=r"(a) : "l"(p));
    return a;
}
#define CP_ASYNC16(dst, src) \
    asm volatile("cp.async.cg.shared.global [%0], [%1], 16;" :: "r"(dst), "l"(src) : "memory")
#define CP_COMMIT() asm volatile("cp.async.commit_group;" ::: "memory")
#define CP_WAIT2()  asm volatile("cp.async.wait_group 2;" ::: "memory")
#define CP_WAIT0()  asm volatile("cp.async.wait_group 0;" ::: "memory")

#define LDSM_X4(r0, r1, r2, r3, a) \
    asm volatile("ldmatrix.sync.aligned.m8n8.x4.shared.b16 {%0,%1,%2,%3}, [%4];" \
        : "=r"(r0), "=r"(r1), "=r"(r2), "=r"(r3) : "r"(a))

#define MMA_BF16(c, a, b) \
    asm volatile("mma.sync.aligned.m16n8k16.row.col.f32.bf16.bf16.f32 " \
        "{%0,%1,%2,%3}, {%4,%5,%6,%7}, {%8,%9}, {%0,%1,%2,%3};" \
        : "+f"((c)[0]), "+f"((c)[1]), "+f"((c)[2]), "+f"((c)[3]) \
        : "r"((a)[0]), "r"((a)[1]), "r"((a)[2]), "r"((a)[3]), "r"((b)[0]), "r"((b)[1]))

#define SW64(o) ((o) ^ (((o) >> 3) & 0x30))

// ---------------------------------------------------------------------------
// Prep kernels
// ---------------------------------------------------------------------------
__global__ __launch_bounds__(256) void prep_W(const float* __restrict__ W) {
    int idx = blockIdx.x * 256 + threadIdx.x;        // 0..327679
    if (idx < GVc) g_acc[idx] = 0.0f;
    float x = W[idx];
    int k = idx / GVc, n = idx % GVc;
    __nv_bfloat16 h = __float2bfloat16_rn(x);
    float r = x - __bfloat162float(h);
    g_Wt_hi[(size_t)n * Hd + k] = h;
    g_Wt_lo[(size_t)n * Hd + k] = __float2bfloat16_rn(r);
}

__global__ __launch_bounds__(256) void prep_A(const float* __restrict__ A) {
    size_t idx = (size_t)blockIdx.x * 256 + threadIdx.x;   // over float4's
    float4 v = reinterpret_cast<const float4*>(A)[idx];
    __nv_bfloat16 h0 = __float2bfloat16_rn(v.x), h1 = __float2bfloat16_rn(v.y);
    __nv_bfloat16 h2 = __float2bfloat16_rn(v.z), h3 = __float2bfloat16_rn(v.w);
    __nv_bfloat162 hi01; hi01.x = h0; hi01.y = h1;
    __nv_bfloat162 hi23; hi23.x = h2; hi23.y = h3;
    __nv_bfloat162 lo01, lo23;
    lo01.x = __float2bfloat16_rn(v.x - __bfloat162float(h0));
    lo01.y = __float2bfloat16_rn(v.y - __bfloat162float(h1));
    lo23.x = __float2bfloat16_rn(v.z - __bfloat162float(h2));
    lo23.y = __float2bfloat16_rn(v.w - __bfloat162float(h3));
    reinterpret_cast<__nv_bfloat162*>(g_A_hi)[idx * 2 + 0] = hi01;
    reinterpret_cast<__nv_bfloat162*>(g_A_hi)[idx * 2 + 1] = hi23;
    reinterpret_cast<__nv_bfloat162*>(g_A_lo)[idx * 2 + 0] = lo01;
    reinterpret_cast<__nv_bfloat162*>(g_A_lo)[idx * 2 + 1] = lo23;
}

// ---------------------------------------------------------------------------
// bf16x3 GEMM: logits[16384,640] = A @ W + bias
// 128x64 CTA tile, BK=32, 4-stage cp.async, SW64 swizzle, 2 CTAs/SM.
// Warps 4(M)x2(N): warp tile 32x32. Cross-k-step fragment double buffering:
// hi fragments for step s+1 prefetched during step s; no MMA follows its LDSM.
// ---------------------------------------------------------------------------
#define NSTAGE 4
#define NCHUNK 16
#define STAGE_BYTES 24576
#define AHI_OFF 0
#define ALO_OFF 8192
#define BHI_OFF 16384
#define BLO_OFF 20480
#define GEMM_SMEM (NSTAGE * STAGE_BYTES + 1024)

__global__ __launch_bounds__(256, 2) void gemm_bf16x3(const float* __restrict__ bias) {
    extern __shared__ char dsm[];
    const uint32_t raw = smem_u32(dsm);
    const uint32_t sb = (raw + 1023u) & ~1023u;

    const int tid = threadIdx.x;
    const int wid = tid >> 5, lane = tid & 31;
    const int rowBase = blockIdx.y * 128;
    const int colBase = blockIdx.x * 64;
    const int warpM = (wid & 3) * 32;        // 4 warps over M=128
    const int warpN = (wid >> 2) * 32;       // 2 warps over N=64

    const __nv_bfloat16* __restrict__ Ah = g_A_hi;
    const __nv_bfloat16* __restrict__ Al = g_A_lo;
    const __nv_bfloat16* __restrict__ Bh = g_Wt_hi;
    const __nv_bfloat16* __restrict__ Bl = g_Wt_lo;

    const int ra0 = tid >> 2,          ca = tid & 3;
    const int ra1 = (tid + 256) >> 2;
    const int rb  = tid >> 2;

    auto load_stage = [&](int ck) {
        const uint32_t so = sb + (ck & 3) * STAGE_BYTES;
        const int kt = ck * 32;
        const uint32_t offA0 = SW64((uint32_t)(ra0 * 64 + ca * 16));
        const uint32_t offA1 = SW64((uint32_t)(ra1 * 64 + ca * 16));
        const uint32_t offB  = SW64((uint32_t)(rb  * 64 + ca * 16));
        CP_ASYNC16(so + AHI_OFF + offA0, &Ah[(size_t)(rowBase + ra0) * Hd + kt + ca * 8]);
        CP_ASYNC16(so + AHI_OFF + offA1, &Ah[(size_t)(rowBase + ra1) * Hd + kt + ca * 8]);
        CP_ASYNC16(so + ALO_OFF + offA0, &Al[(size_t)(rowBase + ra0) * Hd + kt + ca * 8]);
        CP_ASYNC16(so + ALO_OFF + offA1, &Al[(size_t)(rowBase + ra1) * Hd + kt + ca * 8]);
        CP_ASYNC16(so + BHI_OFF + offB,  &Bh[(size_t)(colBase + rb) * Hd + kt + ca * 8]);
        CP_ASYNC16(so + BLO_OFF + offB,  &Bl[(size_t)(colBase + rb) * Hd + kt + ca * 8]);
    };

    float c[2][4][4];
    #pragma unroll
    for (int i = 0; i < 2; i++)
        #pragma unroll
        for (int j = 0; j < 4; j++)
            #pragma unroll
            for (int k = 0; k < 4; k++) c[i][j][k] = 0.0f;

    // Thread-constant swizzled offsets per (kk in {0,16}, atom)
    const uint32_t a_row = warpM + (lane & 15);
    const uint32_t a_colpart = (lane >> 4) * 16;
    const uint32_t b_row = warpN + ((lane >> 4) ? 8u : 0u) + (lane & 7);
    const uint32_t b_colpart = ((lane >> 3) & 1) * 16;
    uint32_t aoffK[2][2], boffK[2][2];
    #pragma unroll
    for (int p = 0; p < 2; p++)
        #pragma unroll
        for (int ma = 0; ma < 2; ma++) {
            aoffK[p][ma] = SW64((a_row + ma * 16) * 64 + p * 32 + a_colpart);
            boffK[p][ma] = SW64((b_row + ma * 16) * 64 + p * 32 + b_colpart);
        }

    // Double-buffered hi fragments
    uint32_t ah[2][2][4], bh[2][4][2];
    uint32_t al[2][4], bl[4][2];

    load_stage(0); CP_COMMIT();
    load_stage(1); CP_COMMIT();
    load_stage(2); CP_COMMIT();

    for (int ck = 0; ck < NCHUNK; ck++) {
        CP_WAIT2();
        __syncthreads();
        if (ck + 3 < NCHUNK) load_stage(ck + 3);
        CP_COMMIT();

        const uint32_t so  = sb + (ck & 3) * STAGE_BYTES;
        const uint32_t soN = sb + ((ck + 1) & 3) * STAGE_BYTES;  // stage ck+1 data ready (wait2)

        if (ck == 0) {
            // initial hi fragments for step (0,0)
            #pragma unroll
            for (int ma = 0; ma < 2; ma++)
                LDSM_X4(ah[0][ma][0], ah[0][ma][1], ah[0][ma][2], ah[0][ma][3],
                        so + AHI_OFF + aoffK[0][ma]);
            #pragma unroll
            for (int pp = 0; pp < 2; pp++) {
                uint32_t q0, q1, q2, q3;
                LDSM_X4(q0, q1, q2, q3, so + BHI_OFF + boffK[0][pp]);
                bh[0][2*pp][0] = q0; bh[0][2*pp][1] = q1;
                bh[0][2*pp+1][0] = q2; bh[0][2*pp+1][1] = q3;
            }
        }

        #pragma unroll
        for (int p = 0; p < 2; p++) {
            const int q = p ^ 1;                     // next-step buffer / kk index
            const uint32_t soPF = (p == 0) ? so : soN;  // prefetch source stage

            // 1) hh MMAs — operands prefetched in previous step
            #pragma unroll
            for (int ma = 0; ma < 2; ma++)
                #pragma unroll
                for (int nb = 0; nb < 4; nb++) MMA_BF16(c[ma][nb], ah[p][ma], bh[p][nb]);

            // 2) LDSM current-step lo fragments
            #pragma unroll
            for (int ma = 0; ma < 2; ma++)
                LDSM_X4(al[ma][0], al[ma][1], al[ma][2], al[ma][3],
                        so + ALO_OFF + aoffK[p][ma]);
            #pragma unroll
            for (int pp = 0; pp < 2; pp++) {
                uint32_t q0, q1, q2, q3;
                LDSM_X4(q0, q1, q2, q3, so + BLO_OFF + boffK[p][pp]);
                bl[2*pp][0] = q0; bl[2*pp][1] = q1;
                bl[2*pp+1][0] = q2; bl[2*pp+1][1] = q3;
            }

            // 3) prefetch next-step hi fragments into buffer q
            #pragma unroll
            for (int ma = 0; ma < 2; ma++)
                LDSM_X4(ah[q][ma][0], ah[q][ma][1], ah[q][ma][2], ah[q][ma][3],
                        soPF + AHI_OFF + aoffK[q][ma]);
            #pragma unroll
            for (int pp = 0; pp < 2; pp++) {
                uint32_t q0, q1, q2, q3;
                LDSM_X4(q0, q1, q2, q3, soPF + BHI_OFF + boffK[q][pp]);
                bh[q][2*pp][0] = q0; bh[q][2*pp][1] = q1;
                bh[q][2*pp+1][0] = q2; bh[q][2*pp+1][1] = q3;
            }

            // 4) lh MMAs (al latency covered by hh MMAs)
            #pragma unroll
            for (int ma = 0; ma < 2; ma++)
                #pragma unroll
                for (int nb = 0; nb < 4; nb++) MMA_BF16(c[ma][nb], al[ma], bh[p][nb]);

            // 5) hl MMAs
            #pragma unroll
            for (int ma = 0; ma < 2; ma++)
                #pragma unroll
                for (int nb = 0; nb < 4; nb++) MMA_BF16(c[ma][nb], ah[p][ma], bl[nb]);
        }
    }
    CP_WAIT0();

    // Epilogue
    float bv[8];
    #pragma unroll
    for (int nb = 0; nb < 4; nb++) {
        int cc = colBase + warpN + nb * 8 + (lane & 3) * 2;
        bv[2*nb]   = bias[cc];
        bv[2*nb+1] = bias[cc + 1];
    }
    #pragma unroll
    for (int ma = 0; ma < 2; ma++) {
        int rr0 = rowBase + warpM + ma * 16 + (lane >> 2);
        #pragma unroll
        for (int nb = 0; nb < 4; nb++) {
            int cc = colBase + warpN + nb * 8 + (lane & 3) * 2;
            float2 v0 = make_float2(c[ma][nb][0] + bv[2*nb], c[ma][nb][1] + bv[2*nb+1]);
            float2 v1 = make_float2(c[ma][nb][2] + bv[2*nb], c[ma][nb][3] + bv[2*nb+1]);
            *reinterpret_cast<float2*>(&g_logits[(size_t)rr0 * GVc + cc]) = v0;
            *reinterpret_cast<float2*>(&g_logits[(size_t)(rr0 + 8) * GVc + cc]) = v1;
        }
    }
}

// ---------------------------------------------------------------------------
// Rows: one warp per (n,g): argmax(l+g) gather + masked softmax marginal
// ---------------------------------------------------------------------------
#define RPB 64

__global__ __launch_bounds__(256) void rows_kernel(
    const float* __restrict__ gumbels,
    const int*   __restrict__ mask,
    const float* __restrict__ codevectors,
    float*       __restrict__ out)
{
    __shared__ float sAcc[GVc];
    const int tid = threadIdx.x, lane = tid & 31, warp = tid >> 5;

    for (int i = tid; i < GVc; i += 256) sAcc[i] = 0.0f;
    __syncthreads();

    const int base = blockIdx.x * RPB;
    for (int rr = warp; rr < RPB; rr += 8) {
        const int row = base + rr;
        const int n = row >> 1, g = row & 1;
        const float* lrow = &g_logits[(size_t)n * GVc + g * Vv];
        const float* grow = &gumbels[(size_t)row * Vv];

        float lv[10], ev[10];
        float bestv = -1e30f; int besti = 0; float mx = -1e30f;
        #pragma unroll
        for (int t = 0; t < 10; t++) {
            int v = lane + 32 * t;
            float x = lrow[v];
            lv[t] = x;
            float s = x + grow[v];
            if (s > bestv) { bestv = s; besti = v; }
            mx = fmaxf(mx, x);
        }
        #pragma unroll
        for (int off = 16; off; off >>= 1) {
            float ov = __shfl_xor_sync(0xffffffffu, bestv, off);
            int   oi = __shfl_xor_sync(0xffffffffu, besti, off);
            if (ov > bestv || (ov == bestv && oi < besti)) { bestv = ov; besti = oi; }
            mx = fmaxf(mx, __shfl_xor_sync(0xffffffffu, mx, off));
        }
        float sum = 0.0f;
        #pragma unroll
        for (int t = 0; t < 10; t++) { ev[t] = __expf(lv[t] - mx); sum += ev[t]; }
        #pragma unroll
        for (int off = 16; off; off >>= 1) sum += __shfl_xor_sync(0xffffffffu, sum, off);
        const float inv = 1.0f / sum;

        if (mask[n] != 0) {
            #pragma unroll
            for (int t = 0; t < 10; t++)
                atomicAdd(&sAcc[g * Vv + lane + 32 * t], ev[t] * inv);
        }
        const float4* src = reinterpret_cast<const float4*>(
            &codevectors[((size_t)g * Vv + besti) * (Dd / Gg)]);
        float4* dst = reinterpret_cast<float4*>(&out[(size_t)n * Dd + g * (Dd / Gg)]);
        dst[lane] = src[lane];
    }
    __syncthreads();
    for (int i = tid; i < GVc; i += 256) atomicAdd(&g_acc[i], sAcc[i]);
}

// ---------------------------------------------------------------------------
// Finalize: mask count + perplexity (640 threads, deterministic)
// ---------------------------------------------------------------------------
__global__ __launch_bounds__(640) void finalize_kernel(
    const int* __restrict__ mask, float* __restrict__ out, int out_size)
{
    __shared__ float  mred[640];
    __shared__ double wsum[20];
    const int tid = threadIdx.x, lane = tid & 31, warp = tid >> 5;

    // mask count: 4096 int4 over 640 threads
    float cnt = 0.0f;
    for (int i = tid; i < Nrows / 4; i += 640) {
        int4 m = reinterpret_cast<const int4*>(mask)[i];
        cnt += (m.x != 0) + (m.y != 0) + (m.z != 0) + (m.w != 0);
    }
    #pragma unroll
    for (int off = 16; off; off >>= 1) cnt += __shfl_xor_sync(0xffffffffu, cnt, off);
    if (lane == 0) mred[warp] = cnt;
    __syncthreads();
    double msum = 0.0;
    for (int w = 0; w < 20; w++) msum += (double)mred[w];

    double marg = (double)g_acc[tid] / msum;
    double t = marg * log(marg + 1e-7);
    #pragma unroll
    for (int off = 16; off; off >>= 1)
        t += __shfl_xor_sync(0xffffffffu, t, off);
    if (lane == 0) wsum[warp] = t;
    __syncthreads();
    if (tid == 0) {
        double e0 = 0.0, e1 = 0.0;
        for (int w = 0; w < 10; w++)  e0 += wsum[w];
        for (int w = 10; w < 20; w++) e1 += wsum[w];
        out[out_size - 1] = (float)(exp(-e0) + exp(-e1));
    }
}

// ---------------------------------------------------------------------------
extern "C" void kernel_launch(void* const* d_in, const int* in_sizes, int n_in,
                              void* d_out, int out_size)
{
    (void)in_sizes; (void)n_in;
    const float* hs   = (const float*)d_in[0];
    const int*   mask = (const int*)  d_in[1];
    const float* W    = (const float*)d_in[2];
    const float* bias = (const float*)d_in[3];
    const float* cb   = (const float*)d_in[4];
    const float* gmb  = (const float*)d_in[5];
    float* out = (float*)d_out;

    static bool attr_set = false;
    if (!attr_set) {
        cudaFuncSetAttribute(gemm_bf16x3, cudaFuncAttributeMaxDynamicSharedMemorySize, GEMM_SMEM);
        attr_set = true;
    }

    prep_W<<<(Hd * GVc) / 256, 256>>>(W);
    prep_A<<<(Nrows * Hd / 4) / 256, 256>>>(hs);

    dim3 ggrid(GVc / 64, Nrows / 128);   // (10, 128) = 1280 CTAs
    gemm_bf16x3<<<ggrid, 256, GEMM_SMEM>>>(bias);

    rows_kernel<<<(Nrows * Gg) / RPB, 256>>>(gmb, mask, cb, out);
    finalize_kernel<<<1, 640>>>(mask, out, out_size);
}